// round 4
// baseline (speedup 1.0000x reference)
#include <cuda_runtime.h>

#define BB 16
#define CC 256
#define LL 8192
#define KK 3
#define NROWS (BB*CC)
#define BN_EPS 1e-5f
#define NTILES 512           // LL/16
#define NBK (BB*NTILES)      // 8192 buckets
#define CAP 4096             // max entries per bucket (256ch * 16col) -- cannot overflow
#define VBLK 96
#define WBLK (KK*CC*CC/256)  // 768 blocks for wT build

// ---- scratch (device globals; no allocation) ----
__device__ float2 g_rp[NROWS];                 // per-row (sum, sumsq)
__device__ float g_vpart[VBLK];                // vnorm partials
__device__ float g_a[CC];
__device__ float g_bb[CC];
__device__ float g_scale;
__device__ __align__(16) float g_wT[KK*CC*CC]; // wT[k][c][o]
__device__ int g_bkCnt[NBK];
__device__ uint2 g_bk[(size_t)NBK*CAP];        // {pack(c<<13|j), val}

// ---- block reduce (256 threads), broadcasts (sum_a, sum_b) to all ----
__device__ __forceinline__ float2 blockReduce2(float a, float b, float* red) {
#pragma unroll
    for (int o = 16; o; o >>= 1) {
        a += __shfl_xor_sync(0xffffffffu, a, o);
        b += __shfl_xor_sync(0xffffffffu, b, o);
    }
    int w = threadIdx.x >> 5, lane = threadIdx.x & 31;
    __syncthreads();
    if (lane == 0) { red[w] = a; red[8 + w] = b; }
    __syncthreads();
    float ra = 0.f, rb = 0.f;
#pragma unroll
    for (int i = 0; i < 8; i++) { ra += red[i]; rb += red[8 + i]; }
    return make_float2(ra, rb);
}

// ==== K1: per-row stats + vnorm partials + zero bucket counters ====
__global__ void __launch_bounds__(256) K1(const float* __restrict__ x, const float* __restrict__ v) {
    __shared__ float red[16];
    int bid = blockIdx.x;
    if (bid < NROWS) {
        const float4* xr = (const float4*)(x + (size_t)bid * LL);
        float s = 0.f, q = 0.f;
#pragma unroll
        for (int i = 0; i < 8; i++) {
            float4 t = xr[threadIdx.x + 256 * i];
            s += (t.x + t.y) + (t.z + t.w);
            q += (t.x * t.x + t.y * t.y) + (t.z * t.z + t.w * t.w);
        }
        float2 r = blockReduce2(s, q, red);
        if (threadIdx.x == 0) g_rp[bid] = r;
        if (threadIdx.x < 2) g_bkCnt[bid * 2 + threadIdx.x] = 0;
    } else {
        int vb = bid - NROWS;
        float s = 0.f;
        for (int i = vb * 256 + threadIdx.x; i < CC * CC * KK; i += VBLK * 256) {
            float t = v[i];
            s += t * t;
        }
        float2 r = blockReduce2(s, 0.f, red);
        if (threadIdx.x == 0) g_vpart[vb] = r.x;
    }
}

// ==== K2: finalize per-channel affine + weight scale (1 block) ====
__global__ void K2(const float* __restrict__ bnw, const float* __restrict__ bnb,
                   const float* __restrict__ g) {
    __shared__ float red[16];
    int c = threadIdx.x;
    float s = 0.f, q = 0.f;
#pragma unroll
    for (int b = 0; b < BB; b++) { float2 p = g_rp[b * CC + c]; s += p.x; q += p.y; }
    const float inv = 1.0f / (float)(BB * LL);
    float mean = s * inv;
    float var = fmaxf(q * inv - mean * mean, 0.f);
    float a = bnw[c] * rsqrtf(var + BN_EPS);
    g_a[c] = a;
    g_bb[c] = fmaf(-mean, a, bnb[c]);
    float vs = (c < VBLK) ? g_vpart[c] : 0.f;
    float2 r = blockReduce2(vs, 0.f, red);
    if (c == 0) g_scale = g[0] * rsqrtf(r.x);
}

// ==== K3: sparsemax rows (blocks < NROWS) + wT build (blocks >= NROWS, 768 blocks) ====
__global__ void __launch_bounds__(256) K3(const float* __restrict__ x, const float* __restrict__ v) {
    int bid = blockIdx.x;
    if (bid >= NROWS) {
        int idx = (bid - NROWS) * 256 + threadIdx.x;   // 0..196607
        float scale = g_scale;
        int k = idx >> 16;
        int rem = idx & 65535;
        int c = rem >> 8;
        int o = rem & 255;
        g_wT[idx] = v[o * (CC * KK) + c * KK + k] * scale;
        return;
    }
    __shared__ float cand[LL];
    __shared__ float red[16];
    __shared__ int cnt;
    __shared__ float sh_tau;

    int row = bid;
    int b = row >> 8;
    int c = row & 255;
    float a = g_a[c], bo = g_bb[c];
    const float4* xr = (const float4*)(x + (size_t)row * LL);
    float z[32];
    float zmax = -1e30f;
#pragma unroll
    for (int i = 0; i < 8; i++) {
        float4 t = xr[threadIdx.x + 256 * i];
        float z0 = fmaf(a, t.x, bo), z1 = fmaf(a, t.y, bo);
        float z2 = fmaf(a, t.z, bo), z3 = fmaf(a, t.w, bo);
        z[4 * i + 0] = z0; z[4 * i + 1] = z1; z[4 * i + 2] = z2; z[4 * i + 3] = z3;
        zmax = fmaxf(zmax, fmaxf(fmaxf(z0, z1), fmaxf(z2, z3)));
    }
#pragma unroll
    for (int o = 16; o; o >>= 1) zmax = fmaxf(zmax, __shfl_xor_sync(0xffffffffu, zmax, o));
    int w = threadIdx.x >> 5, lane = threadIdx.x & 31;
    if (lane == 0) red[w] = zmax;
    if (threadIdx.x == 0) cnt = 0;
    __syncthreads();
    zmax = red[0];
#pragma unroll
    for (int i = 1; i < 8; i++) zmax = fmaxf(zmax, red[i]);

    float lo = zmax - 1.0f, hi = zmax;
    // only z > zmax-1 can be in the support
#pragma unroll
    for (int i = 0; i < 32; i++) {
        if (z[i] > lo) {
            int p = atomicAdd(&cnt, 1);
            cand[p] = z[i];
        }
    }
    __syncthreads();
    int m = cnt;
    float tau;

    if (m <= 32) {
        // single-warp bisection, shfl-only
        if (threadIdx.x < 32) {
            bool act = (lane < m);
            float zi = act ? cand[lane] : 0.f;
            float l = lo, h = hi;
            for (int it = 0; it < 26; it++) {
                float mid = 0.5f * (l + h);
                bool p = act && (zi > mid);
                float ss = p ? zi : 0.f, nn = p ? 1.f : 0.f;
#pragma unroll
                for (int o = 16; o; o >>= 1) {
                    ss += __shfl_xor_sync(0xffffffffu, ss, o);
                    nn += __shfl_xor_sync(0xffffffffu, nn, o);
                }
                float f = ss - mid * nn - 1.0f;
                if (f > 0.f) l = mid; else h = mid;
            }
            bool p = act && (zi > l);
            float ss = p ? zi : 0.f, nn = p ? 1.f : 0.f;
#pragma unroll
            for (int o = 16; o; o >>= 1) {
                ss += __shfl_xor_sync(0xffffffffu, ss, o);
                nn += __shfl_xor_sync(0xffffffffu, nn, o);
            }
            if (lane == 0) sh_tau = (ss - 1.0f) / fmaxf(nn, 1.f);
        }
        __syncthreads();
        tau = sh_tau;
    } else {
        for (int it = 0; it < 26; it++) {
            float mid = 0.5f * (lo + hi);
            float s = 0.f, n = 0.f;
            for (int i = threadIdx.x; i < m; i += 256) {
                float zz = cand[i];
                if (zz > mid) { s += zz; n += 1.f; }
            }
            float2 r = blockReduce2(s, n, red);
            float f = r.x - mid * r.y - 1.0f;
            if (f > 0.f) lo = mid; else hi = mid;
        }
        float s = 0.f, n = 0.f;
        for (int i = threadIdx.x; i < m; i += 256) {
            float zz = cand[i];
            if (zz > lo) { s += zz; n += 1.f; }
        }
        float2 r = blockReduce2(s, n, red);
        tau = (r.x - 1.0f) / fmaxf(r.y, 1.f);
    }

    // emit nonzeros into per-(b, tile) buckets
    int bkbase = b * NTILES;
#pragma unroll
    for (int i = 0; i < 8; i++) {
#pragma unroll
        for (int q = 0; q < 4; q++) {
            float val = z[4 * i + q] - tau;
            if (val > 0.f) {
                int j = 4 * (threadIdx.x + 256 * i) + q;
                int t = j >> 4;
                int p = atomicAdd(&g_bkCnt[bkbase + t], 1);
                g_bk[(size_t)(bkbase + t) * CAP + p] =
                    make_uint2(((unsigned)c << 13) | (unsigned)j, __float_as_uint(val));
            }
        }
    }
}

// ==== K4: sparse scatter conv + relu. block = (tile t, batch b), thread = output channel o ====
__global__ void __launch_bounds__(256) K4(float* __restrict__ y) {
    __shared__ float sacc[256 * 17];   // [o][col], pitch 17 -> conflict-free
    int t = blockIdx.x, b = blockIdx.y;
    int l0 = t * 16;
    int tid = threadIdx.x;

#pragma unroll
    for (int i = 0; i < 17; i++) sacc[tid + 256 * i] = 0.f;
    __syncthreads();

    int base = b * NTILES;
    float* my = &sacc[tid * 17];
#pragma unroll
    for (int dt = -1; dt <= 1; dt++) {
        int tt = t + dt;
        if (tt < 0 || tt >= NTILES) continue;
        int n = g_bkCnt[base + tt];
        const uint2* be = g_bk + (size_t)(base + tt) * CAP;
        for (int e = 0; e < n; e++) {
            uint2 E = be[e];
            int c = E.x >> 13;
            int j = E.x & 8191;
            float val = __uint_as_float(E.y);
            int d = j - l0;
#pragma unroll
            for (int k = 0; k < 3; k++) {
                int col = d + 1 - k;
                if (col >= 0 && col < 16) {
                    float wv = g_wT[(k << 16) + (c << 8) + tid];
                    my[col] = fmaf(wv, val, my[col]);
                }
            }
        }
    }
    __syncthreads();

    // thread o writes its 16 consecutive outputs
    float* yr = y + ((size_t)b * CC + tid) * LL + l0;
    float4 o0, o1, o2, o3;
    o0.x = fmaxf(my[0], 0.f);  o0.y = fmaxf(my[1], 0.f);  o0.z = fmaxf(my[2], 0.f);  o0.w = fmaxf(my[3], 0.f);
    o1.x = fmaxf(my[4], 0.f);  o1.y = fmaxf(my[5], 0.f);  o1.z = fmaxf(my[6], 0.f);  o1.w = fmaxf(my[7], 0.f);
    o2.x = fmaxf(my[8], 0.f);  o2.y = fmaxf(my[9], 0.f);  o2.z = fmaxf(my[10], 0.f); o2.w = fmaxf(my[11], 0.f);
    o3.x = fmaxf(my[12], 0.f); o3.y = fmaxf(my[13], 0.f); o3.z = fmaxf(my[14], 0.f); o3.w = fmaxf(my[15], 0.f);
    float4* y4 = (float4*)yr;
    y4[0] = o0; y4[1] = o1; y4[2] = o2; y4[3] = o3;
}

extern "C" void kernel_launch(void* const* d_in, const int* in_sizes, int n_in,
                              void* d_out, int out_size) {
    const float* x   = (const float*)d_in[0];
    const float* bnw = (const float*)d_in[1];
    const float* bnb = (const float*)d_in[2];
    const float* v   = (const float*)d_in[3];
    const float* g   = (const float*)d_in[4];
    float* y = (float*)d_out;

    K1<<<NROWS + VBLK, 256>>>(x, v);
    K2<<<1, 256>>>(bnw, bnb, g);
    K3<<<NROWS + WBLK, 256>>>(x, v);
    K4<<<dim3(NTILES, BB), 256>>>(y);
}

// round 5
// speedup vs baseline: 2.6556x; 2.6556x over previous
#include <cuda_runtime.h>

#define BB 16
#define CC 256
#define LL 8192
#define KK 3
#define NROWS (BB*CC)
#define BN_EPS 1e-5f
#define NTILES 512           // buckets per batch (16 cols each)
#define NBK (BB*NTILES)
#define CAP 4096             // true max entries per bucket (256ch*16col)
#define VBLK 96
#define WBLK (KK*CC*CC/256)  // 768 blocks for wT build
#define TILE 32              // K4 output columns per block
#define NT2 (LL/TILE)        // 256
#define CAPC 48              // per-column list capacity (fallback if exceeded)

// ---- scratch (device globals; no allocation) ----
__device__ float2 g_rp[NROWS];
__device__ float g_vpart[VBLK];
__device__ float g_a[CC];
__device__ float g_bb[CC];
__device__ float g_scale;
__device__ __align__(16) float g_wT[KK*CC*CC];   // wT[k][c][o]
__device__ int g_bkCnt[NBK];
__device__ __align__(8) uint2 g_bk[(size_t)NBK*CAP]; // {c<<13|j, val}

__device__ __forceinline__ float2 blockReduce2(float a, float b, float* red) {
#pragma unroll
    for (int o = 16; o; o >>= 1) {
        a += __shfl_xor_sync(0xffffffffu, a, o);
        b += __shfl_xor_sync(0xffffffffu, b, o);
    }
    int w = threadIdx.x >> 5, lane = threadIdx.x & 31;
    __syncthreads();
    if (lane == 0) { red[w] = a; red[8 + w] = b; }
    __syncthreads();
    float ra = 0.f, rb = 0.f;
#pragma unroll
    for (int i = 0; i < 8; i++) { ra += red[i]; rb += red[8 + i]; }
    return make_float2(ra, rb);
}

// ==== K1: per-row stats + vnorm partials + zero bucket counters ====
__global__ void __launch_bounds__(256) K1(const float* __restrict__ x, const float* __restrict__ v) {
    __shared__ float red[16];
    int bid = blockIdx.x;
    if (bid < NROWS) {
        const float4* xr = (const float4*)(x + (size_t)bid * LL);
        float s = 0.f, q = 0.f;
#pragma unroll
        for (int i = 0; i < 8; i++) {
            float4 t = xr[threadIdx.x + 256 * i];
            s += (t.x + t.y) + (t.z + t.w);
            q += (t.x * t.x + t.y * t.y) + (t.z * t.z + t.w * t.w);
        }
        float2 r = blockReduce2(s, q, red);
        if (threadIdx.x == 0) g_rp[bid] = r;
        if (threadIdx.x < 2) g_bkCnt[bid * 2 + threadIdx.x] = 0;
    } else {
        int vb = bid - NROWS;
        float s = 0.f;
        for (int i = vb * 256 + threadIdx.x; i < CC * CC * KK; i += VBLK * 256) {
            float t = v[i];
            s += t * t;
        }
        float2 r = blockReduce2(s, 0.f, red);
        if (threadIdx.x == 0) g_vpart[vb] = r.x;
    }
}

// ==== K2: finalize per-channel affine + weight scale (1 block) ====
__global__ void K2(const float* __restrict__ bnw, const float* __restrict__ bnb,
                   const float* __restrict__ g) {
    __shared__ float red[16];
    int c = threadIdx.x;
    float s = 0.f, q = 0.f;
#pragma unroll
    for (int b = 0; b < BB; b++) { float2 p = g_rp[b * CC + c]; s += p.x; q += p.y; }
    const float inv = 1.0f / (float)(BB * LL);
    float mean = s * inv;
    float var = fmaxf(q * inv - mean * mean, 0.f);
    float a = bnw[c] * rsqrtf(var + BN_EPS);
    g_a[c] = a;
    g_bb[c] = fmaf(-mean, a, bnb[c]);
    float vs = (c < VBLK) ? g_vpart[c] : 0.f;
    float2 r = blockReduce2(vs, 0.f, red);
    if (c == 0) g_scale = g[0] * rsqrtf(r.x);
}

// ==== K3: sparsemax (Newton) + bucket emission; tail blocks build wT ====
__global__ void __launch_bounds__(256) K3(const float* __restrict__ x, const float* __restrict__ v) {
    int bid = blockIdx.x;
    if (bid >= NROWS) {
        int idx = (bid - NROWS) * 256 + threadIdx.x;   // 0..196607
        float scale = g_scale;
        int k = idx >> 16;
        int rem = idx & 65535;
        int c = rem >> 8;
        int o = rem & 255;
        g_wT[idx] = v[o * (CC * KK) + c * KK + k] * scale;
        return;
    }
    __shared__ float red[16];
    __shared__ float cand[32];
    __shared__ int cnt;
    __shared__ float sh_tau;

    int row = bid;
    int b = row >> 8;
    int c = row & 255;
    float a = g_a[c], bo = g_bb[c];
    const float4* xr = (const float4*)(x + (size_t)row * LL);
    float z[32];
    float zmax = -1e30f;
#pragma unroll
    for (int i = 0; i < 8; i++) {
        float4 t = xr[threadIdx.x + 256 * i];
        float z0 = fmaf(a, t.x, bo), z1 = fmaf(a, t.y, bo);
        float z2 = fmaf(a, t.z, bo), z3 = fmaf(a, t.w, bo);
        z[4 * i + 0] = z0; z[4 * i + 1] = z1; z[4 * i + 2] = z2; z[4 * i + 3] = z3;
        zmax = fmaxf(zmax, fmaxf(fmaxf(z0, z1), fmaxf(z2, z3)));
    }
#pragma unroll
    for (int o = 16; o; o >>= 1) zmax = fmaxf(zmax, __shfl_xor_sync(0xffffffffu, zmax, o));
    int w = threadIdx.x >> 5, lane = threadIdx.x & 31;
    if (lane == 0) red[w] = zmax;
    if (threadIdx.x == 0) cnt = 0;
    __syncthreads();
    zmax = red[0];
#pragma unroll
    for (int i = 1; i < 8; i++) zmax = fmaxf(zmax, red[i]);

    float lo = zmax - 1.0f;
    // count candidates (only z > zmax-1 can be in the support)
    float cl = 0.f;
#pragma unroll
    for (int i = 0; i < 32; i++) cl += (z[i] > lo) ? 1.f : 0.f;
    float2 mm = blockReduce2(cl, 0.f, red);
    int m = (int)mm.x;
    float tau;

    if (m <= 32) {
        // compact (<=32 atomics total) + single-warp Newton
#pragma unroll
        for (int i = 0; i < 32; i++) {
            if (z[i] > lo) { int p = atomicAdd(&cnt, 1); cand[p] = z[i]; }
        }
        __syncthreads();
        if (threadIdx.x < 32) {
            float zi = (lane < m) ? cand[lane] : -1e30f;
            float t = lo;
            for (int it = 0; it < 16; it++) {
                float d = zi - t;
                float s = d > 0.f ? d : 0.f;
                float n = d > 0.f ? 1.f : 0.f;
#pragma unroll
                for (int o = 16; o; o >>= 1) {
                    s += __shfl_xor_sync(0xffffffffu, s, o);
                    n += __shfl_xor_sync(0xffffffffu, n, o);
                }
                float f = s - 1.0f;
                t += f / fmaxf(n, 1.f);   // Newton step == closed form at convergence
                if (f < 1e-7f) break;
            }
            if (lane == 0) sh_tau = t;
        }
        __syncthreads();
        tau = sh_tau;
    } else {
        // register Newton over all elements (no compaction, no big smem)
        float t = lo;
        for (int it = 0; it < 12; it++) {
            float s = 0.f, n = 0.f;
#pragma unroll
            for (int i = 0; i < 32; i++) {
                float d = z[i] - t;
                if (d > 0.f) { s += d; n += 1.f; }
            }
            float2 r = blockReduce2(s, n, red);
            float f = r.x - 1.0f;
            t += f / fmaxf(r.y, 1.f);
            if (f < 1e-7f) break;          // uniform (reduced values)
        }
        tau = t;
    }

    // emit nonzeros into per-(b, 16-col tile) buckets
    int bkbase = b * NTILES;
#pragma unroll
    for (int i = 0; i < 8; i++) {
#pragma unroll
        for (int q = 0; q < 4; q++) {
            float val = z[4 * i + q] - tau;
            if (val > 0.f) {
                int j = 4 * (threadIdx.x + 256 * i) + q;
                int t2 = j >> 4;
                int p = atomicAdd(&g_bkCnt[bkbase + t2], 1);
                g_bk[(size_t)(bkbase + t2) * CAP + p] =
                    make_uint2(((unsigned)c << 13) | (unsigned)j, __float_as_uint(val));
            }
        }
    }
}

// ==== K4: sparse conv + relu. block = (32-col tile, batch); thread = out channel ====
__global__ void __launch_bounds__(256) K4(float* __restrict__ y) {
    __shared__ int cnt[TILE];
    __shared__ int flag;
    __shared__ __align__(8) uint2 pool[TILE * CAPC];   // per-col contributor lists
    __shared__ float tbuf[CC * 33];                    // [o][col] pitch 33

    int tt = blockIdx.x, b = blockIdx.y;
    int l0 = tt * TILE;
    int tid = threadIdx.x;

    if (tid < TILE) cnt[tid] = 0;
    if (tid == 0) flag = 0;
    __syncthreads();

    int base = b * NTILES;
    int bk0 = 2 * tt - 1; if (bk0 < 0) bk0 = 0;
    int bk1 = 2 * tt + 2; if (bk1 > NTILES - 1) bk1 = NTILES - 1;

    // Phase A: parallel read + decode + bin by output column
    for (int bk = bk0; bk <= bk1; bk++) {
        int n = g_bkCnt[base + bk];
        const uint2* be = g_bk + (size_t)(base + bk) * CAP;
        for (int e = tid; e < n; e += 256) {
            uint2 E = be[e];
            int c = (int)(E.x >> 13);
            int j = (int)(E.x & 8191);
            int d = j - l0 + 1;           // output col for k=0
#pragma unroll
            for (int k = 0; k < 3; k++) {
                int col = d - k;
                if (col >= 0 && col < TILE) {
                    int slot = atomicAdd(&cnt[col], 1);
                    if (slot < CAPC)
                        pool[col * CAPC + slot] =
                            make_uint2((unsigned)((k << 16) | (c << 8)), E.y);
                    else
                        flag = 1;
                }
            }
        }
    }
    __syncthreads();

    if (!flag) {
        // Phase B: register accumulation, 2 columns in flight for ILP
#pragma unroll 1
        for (int c2 = 0; c2 < TILE / 2; c2++) {
            int colA = c2, colB = c2 + TILE / 2;
            int nA = cnt[colA], nB = cnt[colB];
            float accA = 0.f, accB = 0.f;
            const uint2* pA = &pool[colA * CAPC];
            const uint2* pB = &pool[colB * CAPC];
            int nmax = nA > nB ? nA : nB;
            for (int e = 0; e < nmax; e++) {
                if (e < nA) {
                    uint2 E = pA[e];
                    accA = fmaf(g_wT[E.x + tid], __uint_as_float(E.y), accA);
                }
                if (e < nB) {
                    uint2 E = pB[e];
                    accB = fmaf(g_wT[E.x + tid], __uint_as_float(E.y), accB);
                }
            }
            tbuf[tid * 33 + colA] = accA;
            tbuf[tid * 33 + colB] = accB;
        }
    } else {
        // fallback for adversarial density: dynamic smem accumulation
        float* my = &tbuf[tid * 33];
#pragma unroll
        for (int i = 0; i < TILE; i++) my[i] = 0.f;
        for (int bk = bk0; bk <= bk1; bk++) {
            int n = g_bkCnt[base + bk];
            const uint2* be = g_bk + (size_t)(base + bk) * CAP;
            for (int e = 0; e < n; e++) {
                uint2 E = be[e];
                int c = (int)(E.x >> 13);
                int j = (int)(E.x & 8191);
                float val = __uint_as_float(E.y);
                int d = j - l0 + 1;
#pragma unroll
                for (int k = 0; k < 3; k++) {
                    int col = d - k;
                    if (col >= 0 && col < TILE)
                        my[col] = fmaf(g_wT[(k << 16) + (c << 8) + tid], val, my[col]);
                }
            }
        }
    }
    __syncthreads();

    // coalesced output: warp writes one 128B line per iteration, with ReLU
    int warp = tid >> 5, lane = tid & 31;
    float* yb = y + (size_t)b * CC * LL + l0;
#pragma unroll
    for (int r = 0; r < 32; r++) {
        int o = r * 8 + warp;
        float val = tbuf[o * 33 + lane];
        yb[(size_t)o * LL + lane] = fmaxf(val, 0.f);
    }
}

extern "C" void kernel_launch(void* const* d_in, const int* in_sizes, int n_in,
                              void* d_out, int out_size) {
    const float* x   = (const float*)d_in[0];
    const float* bnw = (const float*)d_in[1];
    const float* bnb = (const float*)d_in[2];
    const float* v   = (const float*)d_in[3];
    const float* g   = (const float*)d_in[4];
    float* y = (float*)d_out;

    K1<<<NROWS + VBLK, 256>>>(x, v);
    K2<<<1, 256>>>(bnw, bnb, g);
    K3<<<NROWS + WBLK, 256>>>(x, v);
    K4<<<dim3(NT2, BB), 256>>>(y);
}